// round 7
// baseline (speedup 1.0000x reference)
#include <cuda_runtime.h>
#include <cuda_bf16.h>
#include <cstdint>

// Problem dims (fixed for this dataset)
#define MAXN 100000
#define MAXE 1600000
#define FIN  784
#define D1   128
#define D2   256

// ---------------- scratch (device globals; no allocs allowed) ----------------
__device__ float g_h1[(size_t)MAXN * D1];   // x@W1 (pre-activation)
__device__ float g_g1[(size_t)MAXN * D1];   // relu(gat1)
__device__ float g_h2[(size_t)MAXN * D2];   // g1@W2
__device__ float g_g2[(size_t)MAXN * D2];   // relu(gat2)
__device__ float g_h3[(size_t)MAXN * 2];    // g2@W3
__device__ float g_as[MAXN];                // alpha_src per node (reused per layer)
__device__ float g_ad[MAXN];                // alpha_dst per node
__device__ int   g_counts[MAXN];
__device__ int   g_rowptr[MAXN + 1];
__device__ int   g_colsrc[MAXE];

__device__ __forceinline__ float leaky(float x) { return x > 0.f ? x : 0.2f * x; }

// ---------------- CSR build (edge_index is INT32: jax x64 is disabled) -------
__global__ void hist_kernel(const int* __restrict__ ei, int E) {
    int i = blockIdx.x * blockDim.x + threadIdx.x;
    if (i < E) {
        int d = ei[E + i];
        atomicAdd(&g_counts[d], 1);
    }
}

__global__ void scan_kernel(int N) {
    __shared__ int sums[1024];
    int t = threadIdx.x;
    int chunk = (N + 1023) >> 10;
    int beg = t * chunk, end = min(beg + chunk, N);
    int s = 0;
    for (int i = beg; i < end; i++) s += g_counts[i];
    sums[t] = s;
    __syncthreads();
    for (int off = 1; off < 1024; off <<= 1) {
        int v = (t >= off) ? sums[t - off] : 0;
        __syncthreads();
        sums[t] += v;
        __syncthreads();
    }
    int run = (t == 0) ? 0 : sums[t - 1];
    for (int i = beg; i < end; i++) { g_rowptr[i] = run; run += g_counts[i]; }
    if (t == 0) g_rowptr[N] = sums[1023];
}

__global__ void scatter_kernel(const int* __restrict__ ei, int E) {
    int i = blockIdx.x * blockDim.x + threadIdx.x;
    if (i < E) {
        int s = ei[i];
        int d = ei[E + i];
        int pos = g_rowptr[d] + atomicAdd(&g_counts[d], 1);
        g_colsrc[pos] = s;
    }
}

// ---------------- TF32 tensor-core GEMM: C[M,N] = A[M,K] @ B[K,N] ------------
__device__ __forceinline__ unsigned f2tf32(float x) {
    unsigned r;
    asm("cvt.rna.tf32.f32 %0, %1;" : "=r"(r) : "f"(x));
    return r;
}

__device__ __forceinline__ void mma_tf32(float* c, const unsigned* a, const unsigned* b) {
    asm volatile(
        "mma.sync.aligned.m16n8k8.row.col.f32.tf32.tf32.f32 "
        "{%0,%1,%2,%3}, {%4,%5,%6,%7}, {%8,%9}, {%0,%1,%2,%3};\n"
        : "+f"(c[0]), "+f"(c[1]), "+f"(c[2]), "+f"(c[3])
        : "r"(a[0]), "r"(a[1]), "r"(a[2]), "r"(a[3]), "r"(b[0]), "r"(b[1]));
}

// 128x128 block tile, BK=16, 8 warps (4x2), warp tile 32x64.
// K must be a multiple of 16 (784 and 128 both are). N multiple of 128.
__global__ void __launch_bounds__(256)
gemm_tf32_kernel(const float* __restrict__ A, const float* __restrict__ B,
                 float* __restrict__ C, int M, int N, int K) {
    constexpr int BM = 128, BN = 128, BK = 16;
    constexpr int ASTR = BK + 4;   // 20 -> conflict-free A frag loads
    constexpr int BSTR = BN + 8;   // 136 -> conflict-free B frag loads
    __shared__ unsigned As[BM][ASTR];
    __shared__ unsigned Bs[BK][BSTR];

    int tid = threadIdx.x;
    int wid = tid >> 5, lane = tid & 31;
    int g = lane >> 2, tg = lane & 3;       // groupID, thread-in-group
    int warpM = wid & 3, warpN = wid >> 2;  // 4 x 2 warps
    int m0 = blockIdx.x * BM, n0 = blockIdx.y * BN;
    int wm = warpM * 32, wn = warpN * 64;

    float acc[2][8][4];
#pragma unroll
    for (int mi = 0; mi < 2; mi++)
#pragma unroll
        for (int ni = 0; ni < 8; ni++)
#pragma unroll
            for (int r = 0; r < 4; r++) acc[mi][ni][r] = 0.f;

    for (int k0 = 0; k0 < K; k0 += BK) {
        // load A tile: 128x16, 2 float4 per thread
#pragma unroll
        for (int u = 0; u < 2; u++) {
            int idx = tid + u * 256;
            int row = idx >> 2;
            int cv = (idx & 3) << 2;
            float4 av = make_float4(0.f, 0.f, 0.f, 0.f);
            if (m0 + row < M)
                av = *(const float4*)(A + (size_t)(m0 + row) * K + k0 + cv);
            uint4 tv = make_uint4(f2tf32(av.x), f2tf32(av.y), f2tf32(av.z), f2tf32(av.w));
            *(uint4*)(&As[row][cv]) = tv;
        }
        // load B tile: 16x128, 2 float4 per thread
#pragma unroll
        for (int u = 0; u < 2; u++) {
            int idx = tid + u * 256;
            int row = idx >> 5;
            int col = (idx & 31) << 2;
            float4 bv = *(const float4*)(B + (size_t)(k0 + row) * N + n0 + col);
            uint4 tv = make_uint4(f2tf32(bv.x), f2tf32(bv.y), f2tf32(bv.z), f2tf32(bv.w));
            *(uint4*)(&Bs[row][col]) = tv;
        }
        __syncthreads();

#pragma unroll
        for (int kk = 0; kk < BK; kk += 8) {
            unsigned a[2][4], b[8][2];
#pragma unroll
            for (int mi = 0; mi < 2; mi++) {
                int r = wm + mi * 16;
                a[mi][0] = As[r + g][kk + tg];
                a[mi][1] = As[r + g + 8][kk + tg];
                a[mi][2] = As[r + g][kk + tg + 4];
                a[mi][3] = As[r + g + 8][kk + tg + 4];
            }
#pragma unroll
            for (int ni = 0; ni < 8; ni++) {
                int cb = wn + ni * 8 + g;
                b[ni][0] = Bs[kk + tg][cb];
                b[ni][1] = Bs[kk + tg + 4][cb];
            }
#pragma unroll
            for (int mi = 0; mi < 2; mi++)
#pragma unroll
                for (int ni = 0; ni < 8; ni++)
                    mma_tf32(acc[mi][ni], a[mi], b[ni]);
        }
        __syncthreads();
    }

    // epilogue: write fp32
#pragma unroll
    for (int mi = 0; mi < 2; mi++) {
        int r0 = m0 + wm + mi * 16 + g;
        int r1 = r0 + 8;
#pragma unroll
        for (int ni = 0; ni < 8; ni++) {
            int col = n0 + wn + ni * 8 + tg * 2;
            if (r0 < M)
                *(float2*)(C + (size_t)r0 * N + col) =
                    make_float2(acc[mi][ni][0], acc[mi][ni][1]);
            if (r1 < M)
                *(float2*)(C + (size_t)r1 * N + col) =
                    make_float2(acc[mi][ni][2], acc[mi][ni][3]);
        }
    }
}

// ---------------- alpha_src / alpha_dst: per-node dot products ----------------
template <int D>
__global__ void alpha_kernel(const float* __restrict__ h,
                             const float* __restrict__ a_s,
                             const float* __restrict__ a_d, int N) {
    int v = (blockIdx.x * blockDim.x + threadIdx.x) >> 5;
    if (v >= N) return;
    int lane = threadIdx.x & 31;
    const float4* hv = (const float4*)(h + (size_t)v * D);
    const float4* s4 = (const float4*)a_s;
    const float4* d4 = (const float4*)a_d;
    float ds = 0.f, dd = 0.f;
#pragma unroll
    for (int i = 0; i < D / 128; i++) {
        float4 hh = hv[lane + 32 * i];
        float4 aa = s4[lane + 32 * i];
        float4 bb = d4[lane + 32 * i];
        ds += hh.x * aa.x + hh.y * aa.y + hh.z * aa.z + hh.w * aa.w;
        dd += hh.x * bb.x + hh.y * bb.y + hh.z * bb.z + hh.w * bb.w;
    }
    for (int o = 16; o; o >>= 1) {
        ds += __shfl_xor_sync(~0u, ds, o);
        dd += __shfl_xor_sync(~0u, dd, o);
    }
    if (lane == 0) { g_as[v] = ds; g_ad[v] = dd; }
}

// ---------------- fused GAT aggregation (segment softmax + weighted sum) ----------------
// one warp per destination node; CSR gather; no atomics
template <int D, bool RELU>
__global__ void aggregate_kernel(const float* __restrict__ h,
                                 const float* __restrict__ bias,
                                 float* __restrict__ out, int N) {
    int v = (blockIdx.x * blockDim.x + threadIdx.x) >> 5;
    if (v >= N) return;
    int lane = threadIdx.x & 31;
    float adv = g_ad[v];
    float e_self = leaky(g_as[v] + adv);
    int beg = g_rowptr[v], end = g_rowptr[v + 1];

    // pass 1: max
    float m = e_self;
    for (int j = beg + lane; j < end; j += 32)
        m = fmaxf(m, leaky(g_as[g_colsrc[j]] + adv));
    for (int o = 16; o; o >>= 1) m = fmaxf(m, __shfl_xor_sync(~0u, m, o));

    // pass 2: sum of exp
    float s = 0.f;
    for (int j = beg + lane; j < end; j += 32)
        s += __expf(leaky(g_as[g_colsrc[j]] + adv) - m);
    for (int o = 16; o; o >>= 1) s += __shfl_xor_sync(~0u, s, o);
    float wself = __expf(e_self - m);
    s += wself;
    float invs = 1.f / s;

    // pass 3: weighted accumulate (lanes split feature dim, edges sequential)
    constexpr int V = D / 128;
    float4 acc[V];
    const float4* hv = (const float4*)(h + (size_t)v * D);
#pragma unroll
    for (int i = 0; i < V; i++) {
        float4 t = hv[lane + 32 * i];
        acc[i].x = wself * t.x; acc[i].y = wself * t.y;
        acc[i].z = wself * t.z; acc[i].w = wself * t.w;
    }
    for (int j = beg; j < end; j++) {
        int srcid = g_colsrc[j];
        float w = __expf(leaky(g_as[srcid] + adv) - m);
        const float4* hs = (const float4*)(h + (size_t)srcid * D);
#pragma unroll
        for (int i = 0; i < V; i++) {
            float4 t = hs[lane + 32 * i];
            acc[i].x = fmaf(w, t.x, acc[i].x);
            acc[i].y = fmaf(w, t.y, acc[i].y);
            acc[i].z = fmaf(w, t.z, acc[i].z);
            acc[i].w = fmaf(w, t.w, acc[i].w);
        }
    }
    const float4* b4 = (const float4*)bias;
    float4* o4 = (float4*)(out + (size_t)v * D);
#pragma unroll
    for (int i = 0; i < V; i++) {
        float4 b = b4[lane + 32 * i];
        float4 r;
        r.x = acc[i].x * invs + b.x;
        r.y = acc[i].y * invs + b.y;
        r.z = acc[i].z * invs + b.z;
        r.w = acc[i].w * invs + b.w;
        if (RELU) {
            r.x = fmaxf(r.x, 0.f); r.y = fmaxf(r.y, 0.f);
            r.z = fmaxf(r.z, 0.f); r.w = fmaxf(r.w, 0.f);
        }
        o4[lane + 32 * i] = r;
    }
}

// ---------------- layer 3 projection (256 -> 2) + its alphas ----------------
__global__ void layer3_kernel(const float* __restrict__ g2,
                              const float* __restrict__ W3,
                              const float* __restrict__ a3s,
                              const float* __restrict__ a3d, int N) {
    int v = (blockIdx.x * blockDim.x + threadIdx.x) >> 5;
    if (v >= N) return;
    int lane = threadIdx.x & 31;
    const float* row = g2 + (size_t)v * D2;
    float c0 = 0.f, c1 = 0.f;
#pragma unroll
    for (int i = 0; i < D2 / 32; i++) {
        int k = lane + 32 * i;
        float hv = row[k];
        c0 = fmaf(hv, W3[2 * k], c0);
        c1 = fmaf(hv, W3[2 * k + 1], c1);
    }
    for (int o = 16; o; o >>= 1) {
        c0 += __shfl_xor_sync(~0u, c0, o);
        c1 += __shfl_xor_sync(~0u, c1, o);
    }
    if (lane == 0) {
        g_h3[2 * v] = c0;
        g_h3[2 * v + 1] = c1;
        g_as[v] = c0 * a3s[0] + c1 * a3s[1];
        g_ad[v] = c0 * a3d[0] + c1 * a3d[1];
    }
}

// ---------------- layer 3 aggregation + final class softmax ----------------
__global__ void final_kernel(const float* __restrict__ b3, float* __restrict__ out, int N) {
    int v = (blockIdx.x * blockDim.x + threadIdx.x) >> 5;
    if (v >= N) return;
    int lane = threadIdx.x & 31;
    float adv = g_ad[v];
    float e_self = leaky(g_as[v] + adv);
    int beg = g_rowptr[v], end = g_rowptr[v + 1];

    float m = e_self;
    for (int j = beg + lane; j < end; j += 32)
        m = fmaxf(m, leaky(g_as[g_colsrc[j]] + adv));
    for (int o = 16; o; o >>= 1) m = fmaxf(m, __shfl_xor_sync(~0u, m, o));

    float s = 0.f, a0 = 0.f, a1 = 0.f;
    for (int j = beg + lane; j < end; j += 32) {
        int srcid = g_colsrc[j];
        float w = __expf(leaky(g_as[srcid] + adv) - m);
        s += w;
        a0 = fmaf(w, g_h3[2 * srcid], a0);
        a1 = fmaf(w, g_h3[2 * srcid + 1], a1);
    }
    for (int o = 16; o; o >>= 1) {
        s  += __shfl_xor_sync(~0u, s, o);
        a0 += __shfl_xor_sync(~0u, a0, o);
        a1 += __shfl_xor_sync(~0u, a1, o);
    }
    if (lane == 0) {
        float wself = __expf(e_self - m);
        s += wself;
        a0 += wself * g_h3[2 * v];
        a1 += wself * g_h3[2 * v + 1];
        float invs = 1.f / s;
        float o0 = a0 * invs + b3[0];
        float o1 = a1 * invs + b3[1];
        float mm = fmaxf(o0, o1);
        float z0 = __expf(o0 - mm);
        float z1 = __expf(o1 - mm);
        float zs = z0 + z1;
        out[2 * v]     = z0 / zs;
        out[2 * v + 1] = z1 / zs;
    }
}

// ---------------- launch ----------------
extern "C" void kernel_launch(void* const* d_in, const int* in_sizes, int n_in,
                              void* d_out, int out_size) {
    const float* x   = (const float*)d_in[0];
    const int*   ei  = (const int*)d_in[1];    // int32! (jax x64 disabled)
    // d_in[2] = batch (unused)
    const float* W1  = (const float*)d_in[3];
    const float* a1s = (const float*)d_in[4];
    const float* a1d = (const float*)d_in[5];
    const float* b1  = (const float*)d_in[6];
    const float* W2  = (const float*)d_in[7];
    const float* a2s = (const float*)d_in[8];
    const float* a2d = (const float*)d_in[9];
    const float* b2  = (const float*)d_in[10];
    const float* W3  = (const float*)d_in[11];
    const float* a3s = (const float*)d_in[12];
    const float* a3d = (const float*)d_in[13];
    const float* b3  = (const float*)d_in[14];

    int N = in_sizes[2];        // batch has one entry per node
    int E = in_sizes[1] / 2;

    float *h1, *g1, *h2, *g2;
    int* counts;
    cudaGetSymbolAddress((void**)&h1, g_h1);
    cudaGetSymbolAddress((void**)&g1, g_g1);
    cudaGetSymbolAddress((void**)&h2, g_h2);
    cudaGetSymbolAddress((void**)&g2, g_g2);
    cudaGetSymbolAddress((void**)&counts, g_counts);

    int eb = (E + 255) / 256;
    int nodeWarpBlocks = (N + 7) / 8;   // 8 warps / 256-thread block
    int gemmRows = (N + 127) / 128;

    // CSR build (shared by all 3 layers)
    cudaMemsetAsync(counts, 0, N * sizeof(int));
    hist_kernel<<<eb, 256>>>(ei, E);
    scan_kernel<<<1, 1024>>>(N);
    cudaMemsetAsync(counts, 0, N * sizeof(int));
    scatter_kernel<<<eb, 256>>>(ei, E);

    // layer 1
    gemm_tf32_kernel<<<dim3(gemmRows, 1), 256>>>(x, W1, h1, N, D1, FIN);
    alpha_kernel<D1><<<nodeWarpBlocks, 256>>>(h1, a1s, a1d, N);
    aggregate_kernel<D1, true><<<nodeWarpBlocks, 256>>>(h1, b1, g1, N);

    // layer 2
    gemm_tf32_kernel<<<dim3(gemmRows, 2), 256>>>(g1, W2, h2, N, D2, D1);
    alpha_kernel<D2><<<nodeWarpBlocks, 256>>>(h2, a2s, a2d, N);
    aggregate_kernel<D2, true><<<nodeWarpBlocks, 256>>>(h2, b2, g2, N);

    // layer 3 + output softmax
    layer3_kernel<<<nodeWarpBlocks, 256>>>(g2, W3, a3s, a3d, N);
    final_kernel<<<nodeWarpBlocks, 256>>>(b3, (float*)d_out, N);
}

// round 8
// speedup vs baseline: 1.7864x; 1.7864x over previous
#include <cuda_runtime.h>
#include <cuda_bf16.h>
#include <cstdint>

// Problem dims (fixed for this dataset)
#define MAXN 100000
#define MAXE 1600000
#define FIN  784
#define D1   128
#define D2   256

// ---------------- scratch (device globals; no allocs allowed) ----------------
__device__ float g_h1[(size_t)MAXN * D1];
__device__ float g_g1[(size_t)MAXN * D1];
__device__ float g_h2[(size_t)MAXN * D2];
__device__ float g_g2[(size_t)MAXN * D2];
__device__ float g_h3[(size_t)MAXN * 2];
__device__ float g_as[MAXN];
__device__ float g_ad[MAXN];
__device__ int   g_counts[MAXN];
__device__ int   g_rowptr[MAXN + 1];
__device__ int   g_colsrc[MAXE];

__device__ __forceinline__ float leaky(float x) { return x > 0.f ? x : 0.2f * x; }

// ---------------- CSR build (edge_index is INT32) ----------------
__global__ void hist_kernel(const int* __restrict__ ei, int E) {
    int i = blockIdx.x * blockDim.x + threadIdx.x;
    if (i < E) atomicAdd(&g_counts[ei[E + i]], 1);
}

__global__ void scan_kernel(int N) {
    __shared__ int sums[1024];
    int t = threadIdx.x;
    int chunk = (N + 1023) >> 10;
    int beg = t * chunk, end = min(beg + chunk, N);
    int s = 0;
    for (int i = beg; i < end; i++) s += g_counts[i];
    sums[t] = s;
    __syncthreads();
    for (int off = 1; off < 1024; off <<= 1) {
        int v = (t >= off) ? sums[t - off] : 0;
        __syncthreads();
        sums[t] += v;
        __syncthreads();
    }
    int run = (t == 0) ? 0 : sums[t - 1];
    for (int i = beg; i < end; i++) { g_rowptr[i] = run; run += g_counts[i]; }
    if (t == 0) g_rowptr[N] = sums[1023];
}

__global__ void scatter_kernel(const int* __restrict__ ei, int E) {
    int i = blockIdx.x * blockDim.x + threadIdx.x;
    if (i < E) {
        int s = ei[i];
        int d = ei[E + i];
        int pos = g_rowptr[d] + atomicAdd(&g_counts[d], 1);
        g_colsrc[pos] = s;
    }
}

// ---------------- TF32 tensor-core GEMM, cp.async double-buffered ------------
__device__ __forceinline__ void mma_tf32(float* c, const unsigned* a, const unsigned* b) {
    asm volatile(
        "mma.sync.aligned.m16n8k8.row.col.f32.tf32.tf32.f32 "
        "{%0,%1,%2,%3}, {%4,%5,%6,%7}, {%8,%9}, {%0,%1,%2,%3};\n"
        : "+f"(c[0]), "+f"(c[1]), "+f"(c[2]), "+f"(c[3])
        : "r"(a[0]), "r"(a[1]), "r"(a[2]), "r"(a[3]), "r"(b[0]), "r"(b[1]));
}

__device__ __forceinline__ void cp16(unsigned dst, const void* src, bool valid) {
    asm volatile("cp.async.cg.shared.global [%0], [%1], 16, %2;\n"
                 :: "r"(dst), "l"(src), "r"(valid ? 16 : 0));
}

// 128x128 block tile, BK=16, 8 warps (4x2), warp tile 32x64.
// K multiple of 16, N multiple of 128. Raw fp32 bits fed to tf32 MMA (HW truncates).
__global__ void __launch_bounds__(256)
gemm_tf32_kernel(const float* __restrict__ A, const float* __restrict__ B,
                 float* __restrict__ C, int M, int N, int K) {
    constexpr int BM = 128, BN = 128, BK = 16;
    constexpr int ASTR = BK + 4;   // 20
    constexpr int BSTR = BN + 8;   // 136
    __shared__ float As[2][BM][ASTR];
    __shared__ float Bs[2][BK][BSTR];

    int tid = threadIdx.x;
    int wid = tid >> 5, lane = tid & 31;
    int g = lane >> 2, tg = lane & 3;
    int warpM = wid & 3, warpN = wid >> 2;
    int m0 = blockIdx.x * BM, n0 = blockIdx.y * BN;
    int wm = warpM * 32, wn = warpN * 64;

    float acc[2][8][4];
#pragma unroll
    for (int mi = 0; mi < 2; mi++)
#pragma unroll
        for (int ni = 0; ni < 8; ni++)
#pragma unroll
            for (int r = 0; r < 4; r++) acc[mi][ni][r] = 0.f;

    // per-thread load coordinates
    int ar0 = tid >> 2;            // A rows: 2 chunks of 64
    int ac = (tid & 3) << 2;
    int br0 = tid >> 5;            // B rows: 2 chunks of 8
    int bc = (tid & 31) << 2;

    auto issue = [&](int s, int k0) {
#pragma unroll
        for (int u = 0; u < 2; u++) {
            int row = ar0 + u * 64;
            bool v = (m0 + row) < M;
            unsigned d = (unsigned)__cvta_generic_to_shared(&As[s][row][ac]);
            cp16(d, A + (size_t)(m0 + row) * K + k0 + ac, v);
        }
#pragma unroll
        for (int u = 0; u < 2; u++) {
            int row = br0 + u * 8;
            unsigned d = (unsigned)__cvta_generic_to_shared(&Bs[s][row][bc]);
            cp16(d, B + (size_t)(k0 + row) * N + n0 + bc, true);
        }
        asm volatile("cp.async.commit_group;\n");
    };

    int nk = K / BK;
    issue(0, 0);
    for (int t = 0; t < nk; t++) {
        int s = t & 1;
        if (t + 1 < nk) issue(s ^ 1, (t + 1) * BK);
        else asm volatile("cp.async.commit_group;\n");   // empty group so wait 1 drains current
        asm volatile("cp.async.wait_group 1;\n");
        __syncthreads();

#pragma unroll
        for (int kk = 0; kk < BK; kk += 8) {
            unsigned a[2][4], b[8][2];
#pragma unroll
            for (int mi = 0; mi < 2; mi++) {
                int r = wm + mi * 16;
                a[mi][0] = __float_as_uint(As[s][r + g][kk + tg]);
                a[mi][1] = __float_as_uint(As[s][r + g + 8][kk + tg]);
                a[mi][2] = __float_as_uint(As[s][r + g][kk + tg + 4]);
                a[mi][3] = __float_as_uint(As[s][r + g + 8][kk + tg + 4]);
            }
#pragma unroll
            for (int ni = 0; ni < 8; ni++) {
                int cb = wn + ni * 8 + g;
                b[ni][0] = __float_as_uint(Bs[s][kk + tg][cb]);
                b[ni][1] = __float_as_uint(Bs[s][kk + tg + 4][cb]);
            }
#pragma unroll
            for (int mi = 0; mi < 2; mi++)
#pragma unroll
                for (int ni = 0; ni < 8; ni++)
                    mma_tf32(acc[mi][ni], a[mi], b[ni]);
        }
        __syncthreads();
    }

#pragma unroll
    for (int mi = 0; mi < 2; mi++) {
        int r0 = m0 + wm + mi * 16 + g;
        int r1 = r0 + 8;
#pragma unroll
        for (int ni = 0; ni < 8; ni++) {
            int col = n0 + wn + ni * 8 + tg * 2;
            if (r0 < M)
                *(float2*)(C + (size_t)r0 * N + col) =
                    make_float2(acc[mi][ni][0], acc[mi][ni][1]);
            if (r1 < M)
                *(float2*)(C + (size_t)r1 * N + col) =
                    make_float2(acc[mi][ni][2], acc[mi][ni][3]);
        }
    }
}

// ---------------- alpha_src / alpha_dst ----------------
template <int D>
__global__ void alpha_kernel(const float* __restrict__ h,
                             const float* __restrict__ a_s,
                             const float* __restrict__ a_d, int N) {
    int v = (blockIdx.x * blockDim.x + threadIdx.x) >> 5;
    if (v >= N) return;
    int lane = threadIdx.x & 31;
    const float4* hv = (const float4*)(h + (size_t)v * D);
    const float4* s4 = (const float4*)a_s;
    const float4* d4 = (const float4*)a_d;
    float ds = 0.f, dd = 0.f;
#pragma unroll
    for (int i = 0; i < D / 128; i++) {
        float4 hh = hv[lane + 32 * i];
        float4 aa = s4[lane + 32 * i];
        float4 bb = d4[lane + 32 * i];
        ds += hh.x * aa.x + hh.y * aa.y + hh.z * aa.z + hh.w * aa.w;
        dd += hh.x * bb.x + hh.y * bb.y + hh.z * bb.z + hh.w * bb.w;
    }
    for (int o = 16; o; o >>= 1) {
        ds += __shfl_xor_sync(~0u, ds, o);
        dd += __shfl_xor_sync(~0u, dd, o);
    }
    if (lane == 0) { g_as[v] = ds; g_ad[v] = dd; }
}

// ---------------- fused GAT aggregation ----------------
// one warp per destination; pass-3 unrolled x4 for MLP
template <int D, bool RELU>
__global__ void aggregate_kernel(const float* __restrict__ h,
                                 const float* __restrict__ bias,
                                 float* __restrict__ out, int N) {
    int v = (blockIdx.x * blockDim.x + threadIdx.x) >> 5;
    if (v >= N) return;
    int lane = threadIdx.x & 31;
    float adv = g_ad[v];
    float e_self = leaky(g_as[v] + adv);
    int beg = g_rowptr[v], end = g_rowptr[v + 1];

    // pass 1: max (lanes parallel over edges)
    float m = e_self;
    for (int j = beg + lane; j < end; j += 32)
        m = fmaxf(m, leaky(g_as[g_colsrc[j]] + adv));
    for (int o = 16; o; o >>= 1) m = fmaxf(m, __shfl_xor_sync(~0u, m, o));

    // pass 2: sum of exp
    float s = 0.f;
    for (int j = beg + lane; j < end; j += 32)
        s += __expf(leaky(g_as[g_colsrc[j]] + adv) - m);
    for (int o = 16; o; o >>= 1) s += __shfl_xor_sync(~0u, s, o);
    float wself = __expf(e_self - m);
    s += wself;
    float invs = 1.f / s;

    // pass 3: weighted accumulate, unrolled x4 (lanes split features)
    constexpr int V = D / 128;
    float4 acc[V];
    const float4* hv = (const float4*)(h + (size_t)v * D);
#pragma unroll
    for (int i = 0; i < V; i++) {
        float4 t = hv[lane + 32 * i];
        acc[i].x = wself * t.x; acc[i].y = wself * t.y;
        acc[i].z = wself * t.z; acc[i].w = wself * t.w;
    }
    int j = beg;
    for (; j + 4 <= end; j += 4) {
        int s0 = g_colsrc[j], s1 = g_colsrc[j + 1],
            s2 = g_colsrc[j + 2], s3 = g_colsrc[j + 3];
        float w0 = __expf(leaky(g_as[s0] + adv) - m);
        float w1 = __expf(leaky(g_as[s1] + adv) - m);
        float w2 = __expf(leaky(g_as[s2] + adv) - m);
        float w3 = __expf(leaky(g_as[s3] + adv) - m);
        const float4* p0 = (const float4*)(h + (size_t)s0 * D);
        const float4* p1 = (const float4*)(h + (size_t)s1 * D);
        const float4* p2 = (const float4*)(h + (size_t)s2 * D);
        const float4* p3 = (const float4*)(h + (size_t)s3 * D);
#pragma unroll
        for (int i = 0; i < V; i++) {
            float4 t0 = p0[lane + 32 * i];
            float4 t1 = p1[lane + 32 * i];
            float4 t2 = p2[lane + 32 * i];
            float4 t3 = p3[lane + 32 * i];
            acc[i].x = fmaf(w0, t0.x, acc[i].x); acc[i].y = fmaf(w0, t0.y, acc[i].y);
            acc[i].z = fmaf(w0, t0.z, acc[i].z); acc[i].w = fmaf(w0, t0.w, acc[i].w);
            acc[i].x = fmaf(w1, t1.x, acc[i].x); acc[i].y = fmaf(w1, t1.y, acc[i].y);
            acc[i].z = fmaf(w1, t1.z, acc[i].z); acc[i].w = fmaf(w1, t1.w, acc[i].w);
            acc[i].x = fmaf(w2, t2.x, acc[i].x); acc[i].y = fmaf(w2, t2.y, acc[i].y);
            acc[i].z = fmaf(w2, t2.z, acc[i].z); acc[i].w = fmaf(w2, t2.w, acc[i].w);
            acc[i].x = fmaf(w3, t3.x, acc[i].x); acc[i].y = fmaf(w3, t3.y, acc[i].y);
            acc[i].z = fmaf(w3, t3.z, acc[i].z); acc[i].w = fmaf(w3, t3.w, acc[i].w);
        }
    }
    for (; j < end; j++) {
        int srcid = g_colsrc[j];
        float w = __expf(leaky(g_as[srcid] + adv) - m);
        const float4* hs = (const float4*)(h + (size_t)srcid * D);
#pragma unroll
        for (int i = 0; i < V; i++) {
            float4 t = hs[lane + 32 * i];
            acc[i].x = fmaf(w, t.x, acc[i].x);
            acc[i].y = fmaf(w, t.y, acc[i].y);
            acc[i].z = fmaf(w, t.z, acc[i].z);
            acc[i].w = fmaf(w, t.w, acc[i].w);
        }
    }
    const float4* b4 = (const float4*)bias;
    float4* o4 = (float4*)(out + (size_t)v * D);
#pragma unroll
    for (int i = 0; i < V; i++) {
        float4 b = b4[lane + 32 * i];
        float4 r;
        r.x = acc[i].x * invs + b.x;
        r.y = acc[i].y * invs + b.y;
        r.z = acc[i].z * invs + b.z;
        r.w = acc[i].w * invs + b.w;
        if (RELU) {
            r.x = fmaxf(r.x, 0.f); r.y = fmaxf(r.y, 0.f);
            r.z = fmaxf(r.z, 0.f); r.w = fmaxf(r.w, 0.f);
        }
        o4[lane + 32 * i] = r;
    }
}

// ---------------- layer 3 projection (256 -> 2) + its alphas ----------------
__global__ void layer3_kernel(const float* __restrict__ g2,
                              const float* __restrict__ W3,
                              const float* __restrict__ a3s,
                              const float* __restrict__ a3d, int N) {
    int v = (blockIdx.x * blockDim.x + threadIdx.x) >> 5;
    if (v >= N) return;
    int lane = threadIdx.x & 31;
    const float* row = g2 + (size_t)v * D2;
    float c0 = 0.f, c1 = 0.f;
#pragma unroll
    for (int i = 0; i < D2 / 32; i++) {
        int k = lane + 32 * i;
        float hv = row[k];
        c0 = fmaf(hv, W3[2 * k], c0);
        c1 = fmaf(hv, W3[2 * k + 1], c1);
    }
    for (int o = 16; o; o >>= 1) {
        c0 += __shfl_xor_sync(~0u, c0, o);
        c1 += __shfl_xor_sync(~0u, c1, o);
    }
    if (lane == 0) {
        g_h3[2 * v] = c0;
        g_h3[2 * v + 1] = c1;
        g_as[v] = c0 * a3s[0] + c1 * a3s[1];
        g_ad[v] = c0 * a3d[0] + c1 * a3d[1];
    }
}

// ---------------- layer 3 aggregation + final class softmax ----------------
__global__ void final_kernel(const float* __restrict__ b3, float* __restrict__ out, int N) {
    int v = (blockIdx.x * blockDim.x + threadIdx.x) >> 5;
    if (v >= N) return;
    int lane = threadIdx.x & 31;
    float adv = g_ad[v];
    float e_self = leaky(g_as[v] + adv);
    int beg = g_rowptr[v], end = g_rowptr[v + 1];

    float m = e_self;
    for (int j = beg + lane; j < end; j += 32)
        m = fmaxf(m, leaky(g_as[g_colsrc[j]] + adv));
    for (int o = 16; o; o >>= 1) m = fmaxf(m, __shfl_xor_sync(~0u, m, o));

    float s = 0.f, a0 = 0.f, a1 = 0.f;
    for (int j = beg + lane; j < end; j += 32) {
        int srcid = g_colsrc[j];
        float w = __expf(leaky(g_as[srcid] + adv) - m);
        s += w;
        a0 = fmaf(w, g_h3[2 * srcid], a0);
        a1 = fmaf(w, g_h3[2 * srcid + 1], a1);
    }
    for (int o = 16; o; o >>= 1) {
        s  += __shfl_xor_sync(~0u, s, o);
        a0 += __shfl_xor_sync(~0u, a0, o);
        a1 += __shfl_xor_sync(~0u, a1, o);
    }
    if (lane == 0) {
        float wself = __expf(e_self - m);
        s += wself;
        a0 += wself * g_h3[2 * v];
        a1 += wself * g_h3[2 * v + 1];
        float invs = 1.f / s;
        float o0 = a0 * invs + b3[0];
        float o1 = a1 * invs + b3[1];
        float mm = fmaxf(o0, o1);
        float z0 = __expf(o0 - mm);
        float z1 = __expf(o1 - mm);
        float zs = z0 + z1;
        out[2 * v]     = z0 / zs;
        out[2 * v + 1] = z1 / zs;
    }
}

// ---------------- launch ----------------
extern "C" void kernel_launch(void* const* d_in, const int* in_sizes, int n_in,
                              void* d_out, int out_size) {
    const float* x   = (const float*)d_in[0];
    const int*   ei  = (const int*)d_in[1];    // int32 (jax x64 disabled)
    const float* W1  = (const float*)d_in[3];
    const float* a1s = (const float*)d_in[4];
    const float* a1d = (const float*)d_in[5];
    const float* b1  = (const float*)d_in[6];
    const float* W2  = (const float*)d_in[7];
    const float* a2s = (const float*)d_in[8];
    const float* a2d = (const float*)d_in[9];
    const float* b2  = (const float*)d_in[10];
    const float* W3  = (const float*)d_in[11];
    const float* a3s = (const float*)d_in[12];
    const float* a3d = (const float*)d_in[13];
    const float* b3  = (const float*)d_in[14];

    int N = in_sizes[2];
    int E = in_sizes[1] / 2;

    float *h1, *g1, *h2, *g2;
    int* counts;
    cudaGetSymbolAddress((void**)&h1, g_h1);
    cudaGetSymbolAddress((void**)&g1, g_g1);
    cudaGetSymbolAddress((void**)&h2, g_h2);
    cudaGetSymbolAddress((void**)&g2, g_g2);
    cudaGetSymbolAddress((void**)&counts, g_counts);

    int eb = (E + 255) / 256;
    int nodeWarpBlocks = (N + 7) / 8;
    int gemmRows = (N + 127) / 128;

    // CSR build
    cudaMemsetAsync(counts, 0, N * sizeof(int));
    hist_kernel<<<eb, 256>>>(ei, E);
    scan_kernel<<<1, 1024>>>(N);
    cudaMemsetAsync(counts, 0, N * sizeof(int));
    scatter_kernel<<<eb, 256>>>(ei, E);

    // layer 1
    gemm_tf32_kernel<<<dim3(gemmRows, 1), 256>>>(x, W1, h1, N, D1, FIN);
    alpha_kernel<D1><<<nodeWarpBlocks, 256>>>(h1, a1s, a1d, N);
    aggregate_kernel<D1, true><<<nodeWarpBlocks, 256>>>(h1, b1, g1, N);

    // layer 2
    gemm_tf32_kernel<<<dim3(gemmRows, 2), 256>>>(g1, W2, h2, N, D2, D1);
    alpha_kernel<D2><<<nodeWarpBlocks, 256>>>(h2, a2s, a2d, N);
    aggregate_kernel<D2, true><<<nodeWarpBlocks, 256>>>(h2, b2, g2, N);

    // layer 3 + output softmax
    layer3_kernel<<<nodeWarpBlocks, 256>>>(g2, W3, a3s, a3d, N);
    final_kernel<<<nodeWarpBlocks, 256>>>(b3, (float*)d_out, N);
}

// round 9
// speedup vs baseline: 1.8106x; 1.0136x over previous
#include <cuda_runtime.h>
#include <cuda_bf16.h>
#include <cstdint>

// Problem dims (fixed for this dataset)
#define MAXN 100000
#define MAXE 1600000
#define FIN  784
#define D1   128
#define D2   256

// ---------------- scratch (device globals; no allocs allowed) ----------------
__device__ float g_h1[(size_t)MAXN * D1];
__device__ float g_g1[(size_t)MAXN * D1];
__device__ float g_h2[(size_t)MAXN * D2];
__device__ float g_g2[(size_t)MAXN * D2];
__device__ float g_h3[(size_t)MAXN * 2];
__device__ float g_as[MAXN];
__device__ float g_ad[MAXN];
__device__ int   g_counts[MAXN];
__device__ int   g_rowptr[MAXN + 1];
__device__ int   g_colsrc[MAXE];

__device__ __forceinline__ float leaky(float x) { return x > 0.f ? x : 0.2f * x; }

// ---------------- CSR build (edge_index is INT32) ----------------
__global__ void hist_kernel(const int* __restrict__ ei, int E) {
    int i = blockIdx.x * blockDim.x + threadIdx.x;
    if (i < E) atomicAdd(&g_counts[ei[E + i]], 1);
}

__global__ void scan_kernel(int N) {
    __shared__ int sums[1024];
    int t = threadIdx.x;
    int chunk = (N + 1023) >> 10;
    int beg = t * chunk, end = min(beg + chunk, N);
    int s = 0;
    for (int i = beg; i < end; i++) s += g_counts[i];
    sums[t] = s;
    __syncthreads();
    for (int off = 1; off < 1024; off <<= 1) {
        int v = (t >= off) ? sums[t - off] : 0;
        __syncthreads();
        sums[t] += v;
        __syncthreads();
    }
    int run = (t == 0) ? 0 : sums[t - 1];
    for (int i = beg; i < end; i++) { g_rowptr[i] = run; run += g_counts[i]; }
    if (t == 0) g_rowptr[N] = sums[1023];
}

__global__ void scatter_kernel(const int* __restrict__ ei, int E) {
    int i = blockIdx.x * blockDim.x + threadIdx.x;
    if (i < E) {
        int s = ei[i];
        int d = ei[E + i];
        int pos = g_rowptr[d] + atomicAdd(&g_counts[d], 1);
        g_colsrc[pos] = s;
    }
}

// ---------------- TF32 tensor-core GEMM, 3-stage cp.async pipeline -----------
__device__ __forceinline__ void mma_tf32(float* c, const unsigned* a, const unsigned* b) {
    asm volatile(
        "mma.sync.aligned.m16n8k8.row.col.f32.tf32.tf32.f32 "
        "{%0,%1,%2,%3}, {%4,%5,%6,%7}, {%8,%9}, {%0,%1,%2,%3};\n"
        : "+f"(c[0]), "+f"(c[1]), "+f"(c[2]), "+f"(c[3])
        : "r"(a[0]), "r"(a[1]), "r"(a[2]), "r"(a[3]), "r"(b[0]), "r"(b[1]));
}

__device__ __forceinline__ void cp16(unsigned dst, const void* src, bool valid) {
    asm volatile("cp.async.cg.shared.global [%0], [%1], 16, %2;\n"
                 :: "r"(dst), "l"(src), "r"(valid ? 16 : 0));
}

// 128x128 block tile, BK=16, 8 warps (4x2), warp tile 32x64, 3 smem stages.
// K multiple of 16, N multiple of 128. Raw fp32 bits fed to tf32 MMA.
__global__ void __launch_bounds__(256)
gemm_tf32_kernel(const float* __restrict__ A, const float* __restrict__ B,
                 float* __restrict__ C, int M, int N, int K) {
    constexpr int BM = 128, BN = 128, BK = 16, S = 3;
    constexpr int ASTR = BK + 4;   // 20
    constexpr int BSTR = BN + 8;   // 136
    __shared__ float As[S][BM][ASTR];
    __shared__ float Bs[S][BK][BSTR];

    int tid = threadIdx.x;
    int wid = tid >> 5, lane = tid & 31;
    int g = lane >> 2, tg = lane & 3;
    int warpM = wid & 3, warpN = wid >> 2;
    int m0 = blockIdx.x * BM, n0 = blockIdx.y * BN;
    int wm = warpM * 32, wn = warpN * 64;

    float acc[2][8][4];
#pragma unroll
    for (int mi = 0; mi < 2; mi++)
#pragma unroll
        for (int ni = 0; ni < 8; ni++)
#pragma unroll
            for (int r = 0; r < 4; r++) acc[mi][ni][r] = 0.f;

    int ar0 = tid >> 2;
    int ac = (tid & 3) << 2;
    int br0 = tid >> 5;
    int bc = (tid & 31) << 2;

    auto issue = [&](int s, int k0) {
#pragma unroll
        for (int u = 0; u < 2; u++) {
            int row = ar0 + u * 64;
            bool v = (m0 + row) < M;
            unsigned d = (unsigned)__cvta_generic_to_shared(&As[s][row][ac]);
            cp16(d, A + (size_t)(m0 + row) * K + k0 + ac, v);
        }
#pragma unroll
        for (int u = 0; u < 2; u++) {
            int row = br0 + u * 8;
            unsigned d = (unsigned)__cvta_generic_to_shared(&Bs[s][row][bc]);
            cp16(d, B + (size_t)(k0 + row) * N + n0 + bc, true);
        }
        asm volatile("cp.async.commit_group;\n");
    };

    int nk = K / BK;
    issue(0, 0);
    if (nk > 1) issue(1, BK); else asm volatile("cp.async.commit_group;\n");

    for (int t = 0; t < nk; t++) {
        int s = t % S;
        asm volatile("cp.async.wait_group 1;\n");
        __syncthreads();   // stage t ready; everyone done with stage t-1

        // refill the buffer freed by iteration t-1 while computing stage t
        if (t + 2 < nk) issue((t + 2) % S, (t + 2) * BK);
        else asm volatile("cp.async.commit_group;\n");

#pragma unroll
        for (int kk = 0; kk < BK; kk += 8) {
            unsigned a[2][4], b[8][2];
#pragma unroll
            for (int mi = 0; mi < 2; mi++) {
                int r = wm + mi * 16;
                a[mi][0] = __float_as_uint(As[s][r + g][kk + tg]);
                a[mi][1] = __float_as_uint(As[s][r + g + 8][kk + tg]);
                a[mi][2] = __float_as_uint(As[s][r + g][kk + tg + 4]);
                a[mi][3] = __float_as_uint(As[s][r + g + 8][kk + tg + 4]);
            }
#pragma unroll
            for (int ni = 0; ni < 8; ni++) {
                int cb = wn + ni * 8 + g;
                b[ni][0] = __float_as_uint(Bs[s][kk + tg][cb]);
                b[ni][1] = __float_as_uint(Bs[s][kk + tg + 4][cb]);
            }
#pragma unroll
            for (int mi = 0; mi < 2; mi++)
#pragma unroll
                for (int ni = 0; ni < 8; ni++)
                    mma_tf32(acc[mi][ni], a[mi], b[ni]);
        }
    }
    __syncthreads();

#pragma unroll
    for (int mi = 0; mi < 2; mi++) {
        int r0 = m0 + wm + mi * 16 + g;
        int r1 = r0 + 8;
#pragma unroll
        for (int ni = 0; ni < 8; ni++) {
            int col = n0 + wn + ni * 8 + tg * 2;
            if (r0 < M)
                *(float2*)(C + (size_t)r0 * N + col) =
                    make_float2(acc[mi][ni][0], acc[mi][ni][1]);
            if (r1 < M)
                *(float2*)(C + (size_t)r1 * N + col) =
                    make_float2(acc[mi][ni][2], acc[mi][ni][3]);
        }
    }
}

// ---------------- alpha_src / alpha_dst ----------------
template <int D>
__global__ void alpha_kernel(const float* __restrict__ h,
                             const float* __restrict__ a_s,
                             const float* __restrict__ a_d, int N) {
    int v = (blockIdx.x * blockDim.x + threadIdx.x) >> 5;
    if (v >= N) return;
    int lane = threadIdx.x & 31;
    const float4* hv = (const float4*)(h + (size_t)v * D);
    const float4* s4 = (const float4*)a_s;
    const float4* d4 = (const float4*)a_d;
    float ds = 0.f, dd = 0.f;
#pragma unroll
    for (int i = 0; i < D / 128; i++) {
        float4 hh = hv[lane + 32 * i];
        float4 aa = s4[lane + 32 * i];
        float4 bb = d4[lane + 32 * i];
        ds += hh.x * aa.x + hh.y * aa.y + hh.z * aa.z + hh.w * aa.w;
        dd += hh.x * bb.x + hh.y * bb.y + hh.z * bb.z + hh.w * bb.w;
    }
    for (int o = 16; o; o >>= 1) {
        ds += __shfl_xor_sync(~0u, ds, o);
        dd += __shfl_xor_sync(~0u, dd, o);
    }
    if (lane == 0) { g_as[v] = ds; g_ad[v] = dd; }
}

// ---------------- fused GAT aggregation ----------------
// one warp per destination; 2 passes: max, then fused (sum-exp + weighted accum)
template <int D, bool RELU>
__global__ void aggregate_kernel(const float* __restrict__ h,
                                 const float* __restrict__ bias,
                                 float* __restrict__ out, int N) {
    int v = (blockIdx.x * blockDim.x + threadIdx.x) >> 5;
    if (v >= N) return;
    int lane = threadIdx.x & 31;
    float adv = g_ad[v];
    float e_self = leaky(g_as[v] + adv);
    int beg = g_rowptr[v], end = g_rowptr[v + 1];

    // pass 1: max (lanes parallel over edges)
    float m = e_self;
    for (int j = beg + lane; j < end; j += 32)
        m = fmaxf(m, leaky(g_as[g_colsrc[j]] + adv));
    for (int o = 16; o; o >>= 1) m = fmaxf(m, __shfl_xor_sync(~0u, m, o));

    // pass 2 (fused): every lane walks all edges -> s is lane-redundant (no shuffle)
    constexpr int V = D / 128;
    float wself = __expf(e_self - m);
    float s = wself;
    float4 acc[V];
    const float4* hv = (const float4*)(h + (size_t)v * D);
#pragma unroll
    for (int i = 0; i < V; i++) {
        float4 t = hv[lane + 32 * i];
        acc[i].x = wself * t.x; acc[i].y = wself * t.y;
        acc[i].z = wself * t.z; acc[i].w = wself * t.w;
    }
    int j = beg;
    for (; j + 4 <= end; j += 4) {
        int s0 = g_colsrc[j], s1 = g_colsrc[j + 1],
            s2 = g_colsrc[j + 2], s3 = g_colsrc[j + 3];
        float w0 = __expf(leaky(g_as[s0] + adv) - m);
        float w1 = __expf(leaky(g_as[s1] + adv) - m);
        float w2 = __expf(leaky(g_as[s2] + adv) - m);
        float w3 = __expf(leaky(g_as[s3] + adv) - m);
        s += w0 + w1 + w2 + w3;
        const float4* p0 = (const float4*)(h + (size_t)s0 * D);
        const float4* p1 = (const float4*)(h + (size_t)s1 * D);
        const float4* p2 = (const float4*)(h + (size_t)s2 * D);
        const float4* p3 = (const float4*)(h + (size_t)s3 * D);
#pragma unroll
        for (int i = 0; i < V; i++) {
            float4 t0 = p0[lane + 32 * i];
            float4 t1 = p1[lane + 32 * i];
            float4 t2 = p2[lane + 32 * i];
            float4 t3 = p3[lane + 32 * i];
            acc[i].x = fmaf(w0, t0.x, acc[i].x); acc[i].y = fmaf(w0, t0.y, acc[i].y);
            acc[i].z = fmaf(w0, t0.z, acc[i].z); acc[i].w = fmaf(w0, t0.w, acc[i].w);
            acc[i].x = fmaf(w1, t1.x, acc[i].x); acc[i].y = fmaf(w1, t1.y, acc[i].y);
            acc[i].z = fmaf(w1, t1.z, acc[i].z); acc[i].w = fmaf(w1, t1.w, acc[i].w);
            acc[i].x = fmaf(w2, t2.x, acc[i].x); acc[i].y = fmaf(w2, t2.y, acc[i].y);
            acc[i].z = fmaf(w2, t2.z, acc[i].z); acc[i].w = fmaf(w2, t2.w, acc[i].w);
            acc[i].x = fmaf(w3, t3.x, acc[i].x); acc[i].y = fmaf(w3, t3.y, acc[i].y);
            acc[i].z = fmaf(w3, t3.z, acc[i].z); acc[i].w = fmaf(w3, t3.w, acc[i].w);
        }
    }
    for (; j < end; j++) {
        int srcid = g_colsrc[j];
        float w = __expf(leaky(g_as[srcid] + adv) - m);
        s += w;
        const float4* hs = (const float4*)(h + (size_t)srcid * D);
#pragma unroll
        for (int i = 0; i < V; i++) {
            float4 t = hs[lane + 32 * i];
            acc[i].x = fmaf(w, t.x, acc[i].x);
            acc[i].y = fmaf(w, t.y, acc[i].y);
            acc[i].z = fmaf(w, t.z, acc[i].z);
            acc[i].w = fmaf(w, t.w, acc[i].w);
        }
    }
    float invs = 1.f / s;
    const float4* b4 = (const float4*)bias;
    float4* o4 = (float4*)(out + (size_t)v * D);
#pragma unroll
    for (int i = 0; i < V; i++) {
        float4 b = b4[lane + 32 * i];
        float4 r;
        r.x = acc[i].x * invs + b.x;
        r.y = acc[i].y * invs + b.y;
        r.z = acc[i].z * invs + b.z;
        r.w = acc[i].w * invs + b.w;
        if (RELU) {
            r.x = fmaxf(r.x, 0.f); r.y = fmaxf(r.y, 0.f);
            r.z = fmaxf(r.z, 0.f); r.w = fmaxf(r.w, 0.f);
        }
        o4[lane + 32 * i] = r;
    }
}

// ---------------- layer 3 projection (256 -> 2) + its alphas ----------------
__global__ void layer3_kernel(const float* __restrict__ g2,
                              const float* __restrict__ W3,
                              const float* __restrict__ a3s,
                              const float* __restrict__ a3d, int N) {
    int v = (blockIdx.x * blockDim.x + threadIdx.x) >> 5;
    if (v >= N) return;
    int lane = threadIdx.x & 31;
    const float* row = g2 + (size_t)v * D2;
    float c0 = 0.f, c1 = 0.f;
#pragma unroll
    for (int i = 0; i < D2 / 32; i++) {
        int k = lane + 32 * i;
        float hv = row[k];
        c0 = fmaf(hv, W3[2 * k], c0);
        c1 = fmaf(hv, W3[2 * k + 1], c1);
    }
    for (int o = 16; o; o >>= 1) {
        c0 += __shfl_xor_sync(~0u, c0, o);
        c1 += __shfl_xor_sync(~0u, c1, o);
    }
    if (lane == 0) {
        g_h3[2 * v] = c0;
        g_h3[2 * v + 1] = c1;
        g_as[v] = c0 * a3s[0] + c1 * a3s[1];
        g_ad[v] = c0 * a3d[0] + c1 * a3d[1];
    }
}

// ---------------- layer 3 aggregation + final class softmax ----------------
__global__ void final_kernel(const float* __restrict__ b3, float* __restrict__ out, int N) {
    int v = (blockIdx.x * blockDim.x + threadIdx.x) >> 5;
    if (v >= N) return;
    int lane = threadIdx.x & 31;
    float adv = g_ad[v];
    float e_self = leaky(g_as[v] + adv);
    int beg = g_rowptr[v], end = g_rowptr[v + 1];

    float m = e_self;
    for (int j = beg + lane; j < end; j += 32)
        m = fmaxf(m, leaky(g_as[g_colsrc[j]] + adv));
    for (int o = 16; o; o >>= 1) m = fmaxf(m, __shfl_xor_sync(~0u, m, o));

    float s = 0.f, a0 = 0.f, a1 = 0.f;
    for (int j = beg + lane; j < end; j += 32) {
        int srcid = g_colsrc[j];
        float w = __expf(leaky(g_as[srcid] + adv) - m);
        s += w;
        a0 = fmaf(w, g_h3[2 * srcid], a0);
        a1 = fmaf(w, g_h3[2 * srcid + 1], a1);
    }
    for (int o = 16; o; o >>= 1) {
        s  += __shfl_xor_sync(~0u, s, o);
        a0 += __shfl_xor_sync(~0u, a0, o);
        a1 += __shfl_xor_sync(~0u, a1, o);
    }
    if (lane == 0) {
        float wself = __expf(e_self - m);
        s += wself;
        a0 += wself * g_h3[2 * v];
        a1 += wself * g_h3[2 * v + 1];
        float invs = 1.f / s;
        float o0 = a0 * invs + b3[0];
        float o1 = a1 * invs + b3[1];
        float mm = fmaxf(o0, o1);
        float z0 = __expf(o0 - mm);
        float z1 = __expf(o1 - mm);
        float zs = z0 + z1;
        out[2 * v]     = z0 / zs;
        out[2 * v + 1] = z1 / zs;
    }
}

// ---------------- launch ----------------
extern "C" void kernel_launch(void* const* d_in, const int* in_sizes, int n_in,
                              void* d_out, int out_size) {
    const float* x   = (const float*)d_in[0];
    const int*   ei  = (const int*)d_in[1];    // int32 (jax x64 disabled)
    const float* W1  = (const float*)d_in[3];
    const float* a1s = (const float*)d_in[4];
    const float* a1d = (const float*)d_in[5];
    const float* b1  = (const float*)d_in[6];
    const float* W2  = (const float*)d_in[7];
    const float* a2s = (const float*)d_in[8];
    const float* a2d = (const float*)d_in[9];
    const float* b2  = (const float*)d_in[10];
    const float* W3  = (const float*)d_in[11];
    const float* a3s = (const float*)d_in[12];
    const float* a3d = (const float*)d_in[13];
    const float* b3  = (const float*)d_in[14];

    int N = in_sizes[2];
    int E = in_sizes[1] / 2;

    float *h1, *g1, *h2, *g2;
    int* counts;
    cudaGetSymbolAddress((void**)&h1, g_h1);
    cudaGetSymbolAddress((void**)&g1, g_g1);
    cudaGetSymbolAddress((void**)&h2, g_h2);
    cudaGetSymbolAddress((void**)&g2, g_g2);
    cudaGetSymbolAddress((void**)&counts, g_counts);

    int eb = (E + 255) / 256;
    int nodeWarpBlocks = (N + 7) / 8;
    int gemmRows = (N + 127) / 128;

    // CSR build
    cudaMemsetAsync(counts, 0, N * sizeof(int));
    hist_kernel<<<eb, 256>>>(ei, E);
    scan_kernel<<<1, 1024>>>(N);
    cudaMemsetAsync(counts, 0, N * sizeof(int));
    scatter_kernel<<<eb, 256>>>(ei, E);

    // layer 1
    gemm_tf32_kernel<<<dim3(gemmRows, 1), 256>>>(x, W1, h1, N, D1, FIN);
    alpha_kernel<D1><<<nodeWarpBlocks, 256>>>(h1, a1s, a1d, N);
    aggregate_kernel<D1, true><<<nodeWarpBlocks, 256>>>(h1, b1, g1, N);

    // layer 2
    gemm_tf32_kernel<<<dim3(gemmRows, 2), 256>>>(g1, W2, h2, N, D2, D1);
    alpha_kernel<D2><<<nodeWarpBlocks, 256>>>(h2, a2s, a2d, N);
    aggregate_kernel<D2, true><<<nodeWarpBlocks, 256>>>(h2, b2, g2, N);

    // layer 3 + output softmax
    layer3_kernel<<<nodeWarpBlocks, 256>>>(g2, W3, a3s, a3d, N);
    final_kernel<<<nodeWarpBlocks, 256>>>(b3, (float*)d_out, N);
}

// round 11
// speedup vs baseline: 1.9054x; 1.0523x over previous
#include <cuda_runtime.h>
#include <cuda_fp16.h>
#include <cstdint>

// Problem dims (fixed for this dataset)
#define MAXN 100000
#define MAXE 1600000
#define FIN  784
#define D1   128
#define D2   256

// ---------------- scratch (device globals; no allocs allowed) ----------------
__device__ __half g_h1[(size_t)MAXN * D1];   // x@W1 (fp16, gather payload)
__device__ float  g_g1[(size_t)MAXN * D1];   // relu(gat1)
__device__ __half g_h2[(size_t)MAXN * D2];   // g1@W2 (fp16)
__device__ float  g_g2[(size_t)MAXN * D2];   // relu(gat2)
__device__ float  g_h3[(size_t)MAXN * 2];
__device__ float  g_as[MAXN];                // alpha_src (accumulated by GEMM epilogue)
__device__ float  g_ad[MAXN];                // alpha_dst
__device__ int    g_counts[MAXN];
__device__ int    g_rowptr[MAXN + 1];
__device__ int    g_colsrc[MAXE];

__device__ __forceinline__ float leaky(float x) { return x > 0.f ? x : 0.2f * x; }

// ---------------- CSR build (edge_index is INT32) ----------------
__global__ void hist_kernel(const int* __restrict__ ei, int E) {
    int i = blockIdx.x * blockDim.x + threadIdx.x;
    if (i < E) atomicAdd(&g_counts[ei[E + i]], 1);
}

__global__ void scan_kernel(int N) {
    __shared__ int sums[1024];
    int t = threadIdx.x;
    int chunk = (N + 1023) >> 10;
    int beg = t * chunk, end = min(beg + chunk, N);
    int s = 0;
    for (int i = beg; i < end; i++) s += g_counts[i];
    sums[t] = s;
    __syncthreads();
    for (int off = 1; off < 1024; off <<= 1) {
        int v = (t >= off) ? sums[t - off] : 0;
        __syncthreads();
        sums[t] += v;
        __syncthreads();
    }
    int run = (t == 0) ? 0 : sums[t - 1];
    for (int i = beg; i < end; i++) { g_rowptr[i] = run; run += g_counts[i]; }
    if (t == 0) g_rowptr[N] = sums[1023];
}

__global__ void scatter_kernel(const int* __restrict__ ei, int E) {
    int i = blockIdx.x * blockDim.x + threadIdx.x;
    if (i < E) {
        int s = ei[i];
        int d = ei[E + i];
        int pos = g_rowptr[d] + atomicAdd(&g_counts[d], 1);
        g_colsrc[pos] = s;
    }
}

// ---------------- TF32 GEMM -> fp16 C, fused alpha accumulation --------------
__device__ __forceinline__ void mma_tf32(float* c, const unsigned* a, const unsigned* b) {
    asm volatile(
        "mma.sync.aligned.m16n8k8.row.col.f32.tf32.tf32.f32 "
        "{%0,%1,%2,%3}, {%4,%5,%6,%7}, {%8,%9}, {%0,%1,%2,%3};\n"
        : "+f"(c[0]), "+f"(c[1]), "+f"(c[2]), "+f"(c[3])
        : "r"(a[0]), "r"(a[1]), "r"(a[2]), "r"(a[3]), "r"(b[0]), "r"(b[1]));
}

__device__ __forceinline__ void cp16(unsigned dst, const void* src, bool valid) {
    asm volatile("cp.async.cg.shared.global [%0], [%1], 16, %2;\n"
                 :: "r"(dst), "l"(src), "r"(valid ? 16 : 0));
}

// 128x128 block tile, BK=16, 8 warps (4x2), warp tile 32x64, 3 smem stages.
// C written as fp16; per-row alpha_src/alpha_dst partials atomically accumulated.
__global__ void __launch_bounds__(256)
gemm_tf32_kernel(const float* __restrict__ A, const float* __restrict__ B,
                 __half* __restrict__ C,
                 const float* __restrict__ a_s, const float* __restrict__ a_d,
                 int M, int N, int K) {
    constexpr int BM = 128, BN = 128, BK = 16, S = 3;
    constexpr int ASTR = BK + 4;
    constexpr int BSTR = BN + 8;
    __shared__ float As[S][BM][ASTR];
    __shared__ float Bs[S][BK][BSTR];

    int tid = threadIdx.x;
    int wid = tid >> 5, lane = tid & 31;
    int g = lane >> 2, tg = lane & 3;
    int warpM = wid & 3, warpN = wid >> 2;
    int m0 = blockIdx.x * BM, n0 = blockIdx.y * BN;
    int wm = warpM * 32, wn = warpN * 64;

    float acc[2][8][4];
#pragma unroll
    for (int mi = 0; mi < 2; mi++)
#pragma unroll
        for (int ni = 0; ni < 8; ni++)
#pragma unroll
            for (int r = 0; r < 4; r++) acc[mi][ni][r] = 0.f;

    int ar0 = tid >> 2;
    int ac = (tid & 3) << 2;
    int br0 = tid >> 5;
    int bc = (tid & 31) << 2;

    auto issue = [&](int s, int k0) {
#pragma unroll
        for (int u = 0; u < 2; u++) {
            int row = ar0 + u * 64;
            bool v = (m0 + row) < M;
            unsigned d = (unsigned)__cvta_generic_to_shared(&As[s][row][ac]);
            cp16(d, A + (size_t)(m0 + row) * K + k0 + ac, v);
        }
#pragma unroll
        for (int u = 0; u < 2; u++) {
            int row = br0 + u * 8;
            unsigned d = (unsigned)__cvta_generic_to_shared(&Bs[s][row][bc]);
            cp16(d, B + (size_t)(k0 + row) * N + n0 + bc, true);
        }
        asm volatile("cp.async.commit_group;\n");
    };

    int nk = K / BK;
    issue(0, 0);
    if (nk > 1) issue(1, BK); else asm volatile("cp.async.commit_group;\n");

    for (int t = 0; t < nk; t++) {
        int s = t % S;
        asm volatile("cp.async.wait_group 1;\n");
        __syncthreads();
        if (t + 2 < nk) issue((t + 2) % S, (t + 2) * BK);
        else asm volatile("cp.async.commit_group;\n");

#pragma unroll
        for (int kk = 0; kk < BK; kk += 8) {
            unsigned a[2][4], b[8][2];
#pragma unroll
            for (int mi = 0; mi < 2; mi++) {
                int r = wm + mi * 16;
                a[mi][0] = __float_as_uint(As[s][r + g][kk + tg]);
                a[mi][1] = __float_as_uint(As[s][r + g + 8][kk + tg]);
                a[mi][2] = __float_as_uint(As[s][r + g][kk + tg + 4]);
                a[mi][3] = __float_as_uint(As[s][r + g + 8][kk + tg + 4]);
            }
#pragma unroll
            for (int ni = 0; ni < 8; ni++) {
                int cb = wn + ni * 8 + g;
                b[ni][0] = __float_as_uint(Bs[s][kk + tg][cb]);
                b[ni][1] = __float_as_uint(Bs[s][kk + tg + 4][cb]);
            }
#pragma unroll
            for (int mi = 0; mi < 2; mi++)
#pragma unroll
                for (int ni = 0; ni < 8; ni++)
                    mma_tf32(acc[mi][ni], a[mi], b[ni]);
        }
    }
    __syncthreads();

    // epilogue: fp16 C + fused alpha partials
#pragma unroll
    for (int mi = 0; mi < 2; mi++) {
        int r0 = m0 + wm + mi * 16 + g;
        int r1 = r0 + 8;
        float ps0 = 0.f, pd0 = 0.f, ps1 = 0.f, pd1 = 0.f;
#pragma unroll
        for (int ni = 0; ni < 8; ni++) {
            int col = n0 + wn + ni * 8 + tg * 2;
            float s0 = a_s[col], s1 = a_s[col + 1];
            float d0 = a_d[col], d1 = a_d[col + 1];
            ps0 += acc[mi][ni][0] * s0 + acc[mi][ni][1] * s1;
            pd0 += acc[mi][ni][0] * d0 + acc[mi][ni][1] * d1;
            ps1 += acc[mi][ni][2] * s0 + acc[mi][ni][3] * s1;
            pd1 += acc[mi][ni][2] * d0 + acc[mi][ni][3] * d1;
            if (r0 < M)
                *(__half2*)(C + (size_t)r0 * N + col) =
                    __floats2half2_rn(acc[mi][ni][0], acc[mi][ni][1]);
            if (r1 < M)
                *(__half2*)(C + (size_t)r1 * N + col) =
                    __floats2half2_rn(acc[mi][ni][2], acc[mi][ni][3]);
        }
        // reduce over the 4-thread tg group (lane bits 0..1)
        ps0 += __shfl_xor_sync(~0u, ps0, 1); ps0 += __shfl_xor_sync(~0u, ps0, 2);
        pd0 += __shfl_xor_sync(~0u, pd0, 1); pd0 += __shfl_xor_sync(~0u, pd0, 2);
        ps1 += __shfl_xor_sync(~0u, ps1, 1); ps1 += __shfl_xor_sync(~0u, ps1, 2);
        pd1 += __shfl_xor_sync(~0u, pd1, 1); pd1 += __shfl_xor_sync(~0u, pd1, 2);
        if (tg == 0) {
            if (r0 < M) { atomicAdd(&g_as[r0], ps0); atomicAdd(&g_ad[r0], pd0); }
            if (r1 < M) { atomicAdd(&g_as[r1], ps1); atomicAdd(&g_ad[r1], pd1); }
        }
    }
}

// ---------------- fused GAT aggregation (fp16 h gathers) ----------------
// one warp per destination; pass 1: max; pass 2 fused: sum-exp + weighted accum
template <int D, bool RELU>
__global__ void aggregate_kernel(const __half* __restrict__ h,
                                 const float* __restrict__ bias,
                                 float* __restrict__ out, int N) {
    int v = (blockIdx.x * blockDim.x + threadIdx.x) >> 5;
    if (v >= N) return;
    int lane = threadIdx.x & 31;
    float adv = g_ad[v];
    float e_self = leaky(g_as[v] + adv);
    int beg = g_rowptr[v], end = g_rowptr[v + 1];

    // pass 1: max (lanes parallel over edges)
    float m = e_self;
    for (int j = beg + lane; j < end; j += 32)
        m = fmaxf(m, leaky(g_as[g_colsrc[j]] + adv));
    for (int o = 16; o; o >>= 1) m = fmaxf(m, __shfl_xor_sync(~0u, m, o));

    // pass 2: every lane walks all edges; s is lane-redundant
    constexpr int H2 = D / 64;            // half2 elements per lane (2 for D1, 4 for D2)
    float wself = __expf(e_self - m);
    float s = wself;
    float2 acc[H2];
    {
        const __half2* hr = (const __half2*)(h + (size_t)v * D);
#pragma unroll
        for (int i = 0; i < H2; i++) {
            float2 t = __half22float2(hr[lane * H2 + i]);
            acc[i].x = wself * t.x; acc[i].y = wself * t.y;
        }
    }
    int j = beg;
    for (; j + 4 <= end; j += 4) {
        int s0 = g_colsrc[j], s1 = g_colsrc[j + 1],
            s2 = g_colsrc[j + 2], s3 = g_colsrc[j + 3];
        float w0 = __expf(leaky(g_as[s0] + adv) - m);
        float w1 = __expf(leaky(g_as[s1] + adv) - m);
        float w2 = __expf(leaky(g_as[s2] + adv) - m);
        float w3 = __expf(leaky(g_as[s3] + adv) - m);
        s += w0 + w1 + w2 + w3;
        const __half2* p0 = (const __half2*)(h + (size_t)s0 * D);
        const __half2* p1 = (const __half2*)(h + (size_t)s1 * D);
        const __half2* p2 = (const __half2*)(h + (size_t)s2 * D);
        const __half2* p3 = (const __half2*)(h + (size_t)s3 * D);
#pragma unroll
        for (int i = 0; i < H2; i++) {
            float2 t0 = __half22float2(p0[lane * H2 + i]);
            float2 t1 = __half22float2(p1[lane * H2 + i]);
            float2 t2 = __half22float2(p2[lane * H2 + i]);
            float2 t3 = __half22float2(p3[lane * H2 + i]);
            acc[i].x = fmaf(w0, t0.x, acc[i].x); acc[i].y = fmaf(w0, t0.y, acc[i].y);
            acc[i].x = fmaf(w1, t1.x, acc[i].x); acc[i].y = fmaf(w1, t1.y, acc[i].y);
            acc[i].x = fmaf(w2, t2.x, acc[i].x); acc[i].y = fmaf(w2, t2.y, acc[i].y);
            acc[i].x = fmaf(w3, t3.x, acc[i].x); acc[i].y = fmaf(w3, t3.y, acc[i].y);
        }
    }
    for (; j < end; j++) {
        int srcid = g_colsrc[j];
        float w = __expf(leaky(g_as[srcid] + adv) - m);
        s += w;
        const __half2* hs = (const __half2*)(h + (size_t)srcid * D);
#pragma unroll
        for (int i = 0; i < H2; i++) {
            float2 t = __half22float2(hs[lane * H2 + i]);
            acc[i].x = fmaf(w, t.x, acc[i].x);
            acc[i].y = fmaf(w, t.y, acc[i].y);
        }
    }
    float invs = 1.f / s;
    const float2* b2p = (const float2*)bias;
    float2* o2p = (float2*)(out + (size_t)v * D);
#pragma unroll
    for (int i = 0; i < H2; i++) {
        float2 b = b2p[lane * H2 + i];
        float2 r;
        r.x = acc[i].x * invs + b.x;
        r.y = acc[i].y * invs + b.y;
        if (RELU) { r.x = fmaxf(r.x, 0.f); r.y = fmaxf(r.y, 0.f); }
        o2p[lane * H2 + i] = r;
    }
}

// ---------------- layer 3 projection (256 -> 2) + its alphas ----------------
__global__ void layer3_kernel(const float* __restrict__ g2,
                              const float* __restrict__ W3,
                              const float* __restrict__ a3s,
                              const float* __restrict__ a3d, int N) {
    int v = (blockIdx.x * blockDim.x + threadIdx.x) >> 5;
    if (v >= N) return;
    int lane = threadIdx.x & 31;
    const float* row = g2 + (size_t)v * D2;
    float c0 = 0.f, c1 = 0.f;
#pragma unroll
    for (int i = 0; i < D2 / 32; i++) {
        int k = lane + 32 * i;
        float hv = row[k];
        c0 = fmaf(hv, W3[2 * k], c0);
        c1 = fmaf(hv, W3[2 * k + 1], c1);
    }
    for (int o = 16; o; o >>= 1) {
        c0 += __shfl_xor_sync(~0u, c0, o);
        c1 += __shfl_xor_sync(~0u, c1, o);
    }
    if (lane == 0) {
        g_h3[2 * v] = c0;
        g_h3[2 * v + 1] = c1;
        g_as[v] = c0 * a3s[0] + c1 * a3s[1];
        g_ad[v] = c0 * a3d[0] + c1 * a3d[1];
    }
}

// ---------------- layer 3 aggregation + final class softmax ----------------
__global__ void final_kernel(const float* __restrict__ b3, float* __restrict__ out, int N) {
    int v = (blockIdx.x * blockDim.x + threadIdx.x) >> 5;
    if (v >= N) return;
    int lane = threadIdx.x & 31;
    float adv = g_ad[v];
    float e_self = leaky(g_as[v] + adv);
    int beg = g_rowptr[v], end = g_rowptr[v + 1];

    float m = e_self;
    for (int j = beg + lane; j < end; j += 32)
        m = fmaxf(m, leaky(g_as[g_colsrc[j]] + adv));
    for (int o = 16; o; o >>= 1) m = fmaxf(m, __shfl_xor_sync(~0u, m, o));

    float s = 0.f, a0 = 0.f, a1 = 0.f;
    for (int j = beg + lane; j < end; j += 32) {
        int srcid = g_colsrc[j];
        float w = __expf(leaky(g_as[srcid] + adv) - m);
        s += w;
        a0 = fmaf(w, g_h3[2 * srcid], a0);
        a1 = fmaf(w, g_h3[2 * srcid + 1], a1);
    }
    for (int o = 16; o; o >>= 1) {
        s  += __shfl_xor_sync(~0u, s, o);
        a0 += __shfl_xor_sync(~0u, a0, o);
        a1 += __shfl_xor_sync(~0u, a1, o);
    }
    if (lane == 0) {
        float wself = __expf(e_self - m);
        s += wself;
        a0 += wself * g_h3[2 * v];
        a1 += wself * g_h3[2 * v + 1];
        float invs = 1.f / s;
        float o0 = a0 * invs + b3[0];
        float o1 = a1 * invs + b3[1];
        float mm = fmaxf(o0, o1);
        float z0 = __expf(o0 - mm);
        float z1 = __expf(o1 - mm);
        float zs = z0 + z1;
        out[2 * v]     = z0 / zs;
        out[2 * v + 1] = z1 / zs;
    }
}

// ---------------- launch ----------------
extern "C" void kernel_launch(void* const* d_in, const int* in_sizes, int n_in,
                              void* d_out, int out_size) {
    const float* x   = (const float*)d_in[0];
    const int*   ei  = (const int*)d_in[1];    // int32 (jax x64 disabled)
    const float* W1  = (const float*)d_in[3];
    const float* a1s = (const float*)d_in[4];
    const float* a1d = (const float*)d_in[5];
    const float* b1  = (const float*)d_in[6];
    const float* W2  = (const float*)d_in[7];
    const float* a2s = (const float*)d_in[8];
    const float* a2d = (const float*)d_in[9];
    const float* b2  = (const float*)d_in[10];
    const float* W3  = (const float*)d_in[11];
    const float* a3s = (const float*)d_in[12];
    const float* a3d = (const float*)d_in[13];
    const float* b3  = (const float*)d_in[14];

    int N = in_sizes[2];
    int E = in_sizes[1] / 2;

    __half *h1, *h2;
    float *g1, *g2, *as, *ad;
    int* counts;
    cudaGetSymbolAddress((void**)&h1, g_h1);
    cudaGetSymbolAddress((void**)&g1, g_g1);
    cudaGetSymbolAddress((void**)&h2, g_h2);
    cudaGetSymbolAddress((void**)&g2, g_g2);
    cudaGetSymbolAddress((void**)&as, g_as);
    cudaGetSymbolAddress((void**)&ad, g_ad);
    cudaGetSymbolAddress((void**)&counts, g_counts);

    int eb = (E + 255) / 256;
    int nodeWarpBlocks = (N + 7) / 8;
    int gemmRows = (N + 127) / 128;

    // CSR build
    cudaMemsetAsync(counts, 0, N * sizeof(int));
    hist_kernel<<<eb, 256>>>(ei, E);
    scan_kernel<<<1, 1024>>>(N);
    cudaMemsetAsync(counts, 0, N * sizeof(int));
    scatter_kernel<<<eb, 256>>>(ei, E);

    // layer 1 (alpha fused into GEMM epilogue; zero accumulators first)
    cudaMemsetAsync(as, 0, N * sizeof(float));
    cudaMemsetAsync(ad, 0, N * sizeof(float));
    gemm_tf32_kernel<<<dim3(gemmRows, 1), 256>>>(x, W1, h1, a1s, a1d, N, D1, FIN);
    aggregate_kernel<D1, true><<<nodeWarpBlocks, 256>>>(h1, b1, g1, N);

    // layer 2
    cudaMemsetAsync(as, 0, N * sizeof(float));
    cudaMemsetAsync(ad, 0, N * sizeof(float));
    gemm_tf32_kernel<<<dim3(gemmRows, 2), 256>>>(g1, W2, h2, a2s, a2d, N, D2, D1);
    aggregate_kernel<D2, true><<<nodeWarpBlocks, 256>>>(h2, b2, g2, N);

    // layer 3 + output softmax
    layer3_kernel<<<nodeWarpBlocks, 256>>>(g2, W3, a3s, a3d, N);
    final_kernel<<<nodeWarpBlocks, 256>>>(b3, (float*)d_out, N);
}